// round 15
// baseline (speedup 1.0000x reference)
#include <cuda_runtime.h>
#include <cuda_bf16.h>
#include <cuda_fp16.h>
#include <cstdint>

#define N_NODES 100000
#define N_EDGES 1600000
#define F_IN    128
#define F_HID   128
#define F_OUT   64

typedef unsigned long long u64;

// ---------------- packed f32x2 helpers ----------------
__device__ __forceinline__ u64 pack2(float lo, float hi) {
    u64 r; asm("mov.b64 %0, {%1, %2};" : "=l"(r) : "f"(lo), "f"(hi)); return r;
}
__device__ __forceinline__ void fma2(u64& d, u64 a, u64 b) {
    asm("fma.rn.f32x2 %0, %1, %2, %3;" : "=l"(d) : "l"(a), "l"(b), "l"(d));
}
__device__ __forceinline__ void unpack2(u64 v, float& lo, float& hi) {
    asm("mov.b64 {%0, %1}, %2;" : "=f"(lo), "=f"(hi) : "l"(v));
}
__device__ __forceinline__ uint32_t packbf(__nv_bfloat16 a, __nv_bfloat16 b) {
    return ((uint32_t)__bfloat16_as_ushort(b) << 16) | __bfloat16_as_ushort(a);
}
__device__ __forceinline__ void mma_bf16(float* d, const uint32_t* a, const uint32_t* b) {
    asm volatile(
        "mma.sync.aligned.m16n8k16.row.col.f32.bf16.bf16.f32 "
        "{%0,%1,%2,%3}, {%4,%5,%6,%7}, {%8,%9}, {%0,%1,%2,%3};"
        : "+f"(d[0]), "+f"(d[1]), "+f"(d[2]), "+f"(d[3])
        : "r"(a[0]), "r"(a[1]), "r"(a[2]), "r"(a[3]), "r"(b[0]), "r"(b[1]));
}

// ---------------- static device scratch ----------------
// g_cnt relies on CUDA zero-init at module load for the FIRST call;
// k_scan_all re-zeroes it each call for the next call (deterministic).
__device__ int   g_cnt[N_NODES];
__device__ int   g_off[N_NODES + 1];
__device__ int   g_cur[N_NODES];
__device__ int   g_srcs[N_EDGES];
__device__ float g_dinv[N_NODES];
__device__ __align__(16) __half g_hs1h[N_NODES * F_HID];   // fp16 dinv-scaled x@W1
__device__ __align__(16) float  g_agg1[N_NODES * F_HID];   // relu(layer1 out), fp32
__device__ __align__(16) __half g_hs2h[N_NODES * F_OUT];   // fp16 dinv-scaled agg1@W2

// ---------------- CSR: histogram ----------------
__global__ void k_hist(const int* __restrict__ ei) {
    int e4 = blockIdx.x * blockDim.x + threadIdx.x;
    if (e4 * 4 < N_EDGES) {
        int4 d = *(const int4*)&ei[N_EDGES + e4 * 4];
        if ((unsigned)d.x < N_NODES) atomicAdd(&g_cnt[d.x], 1);
        if ((unsigned)d.y < N_NODES) atomicAdd(&g_cnt[d.y], 1);
        if ((unsigned)d.z < N_NODES) atomicAdd(&g_cnt[d.z], 1);
        if ((unsigned)d.w < N_NODES) atomicAdd(&g_cnt[d.w], 1);
    }
}

// ---------------- CSR: scan + dinv + cursors + re-zero cnt ----------------
__global__ void k_scan_all() {
    __shared__ int sm[1024];
    const int t = threadIdx.x;
    const int SEG = (N_NODES + 1023) / 1024;
    int s = t * SEG;
    int epos = min(s + SEG, N_NODES);
    int sum = 0;
    for (int i = s; i < epos; i++) sum += g_cnt[i];
    sm[t] = sum;
    for (int d = 1; d < 1024; d <<= 1) {
        __syncthreads();
        int v = (t >= d) ? sm[t - d] : 0;
        __syncthreads();
        sm[t] += v;
    }
    __syncthreads();
    int run = sm[t] - sum;
    for (int i = s; i < epos; i++) {
        int c = g_cnt[i];
        g_cnt[i]  = 0;                 // re-zero for the NEXT kernel_launch call
        g_off[i]  = run;
        g_cur[i]  = run;
        g_dinv[i] = rsqrtf((float)(c + 1));
        run += c;
    }
    if (t == 1023) g_off[N_NODES] = sm[1023];
}

// ================= fused: CSR fill + layer-1 split-bf16 mma.sync GEMM =================
// All blocks: fill a slice of g_srcs. Blocks < NB_G additionally compute the
// 128x128 tile hs1h[m,n] = fp16(dinv[m] * (x[m,:]@W1[:,n])).
#define NB_G  ((N_NODES + 127) / 128)          // 782
#define NB_E4 ((N_EDGES / 4 + 255) / 256)      // 1563

__global__ __launch_bounds__(256) void k_mma1_fill(
    const float* __restrict__ A, const int* __restrict__ ei,
    const float* __restrict__ W1g)
{
    // ---------- fill slice (all blocks) ----------
    {
        int e4 = blockIdx.x * blockDim.x + threadIdx.x;
        if (e4 * 4 < N_EDGES) {
            int4 s = *(const int4*)&ei[e4 * 4];
            int4 d = *(const int4*)&ei[N_EDGES + e4 * 4];
            if ((unsigned)d.x < N_NODES && (unsigned)s.x < N_NODES)
                g_srcs[atomicAdd(&g_cur[d.x], 1)] = s.x;
            if ((unsigned)d.y < N_NODES && (unsigned)s.y < N_NODES)
                g_srcs[atomicAdd(&g_cur[d.y], 1)] = s.y;
            if ((unsigned)d.z < N_NODES && (unsigned)s.z < N_NODES)
                g_srcs[atomicAdd(&g_cur[d.z], 1)] = s.z;
            if ((unsigned)d.w < N_NODES && (unsigned)s.w < N_NODES)
                g_srcs[atomicAdd(&g_cur[d.w], 1)] = s.w;
        }
    }
    if (blockIdx.x >= NB_G) return;

    // ---------- layer-1 GEMM tile ----------
    constexpr int NW = F_HID;
    constexpr int K  = 128;
    constexpr int KC = 32;
    constexpr int SA = KC + 8;
    constexpr int SW = K + 8;
    constexpr int WN = NW / 4;        // 32
    constexpr int NF = WN / 8;        // 4
    constexpr int OFF_AH = 0;
    constexpr int OFF_AL = 128 * SA * 2;
    constexpr int OFF_WH = 2 * 128 * SA * 2;
    constexpr int OFF_WL = OFF_WH + NW * SW * 2;

    extern __shared__ __align__(16) char sm[];
    const int tid  = threadIdx.x;
    const int wid  = tid >> 5;
    const int lane = tid & 31;
    const int mw   = wid >> 2;
    const int nw   = wid & 3;
    const int rowBase = blockIdx.x * 128;

    // W1 split/transpose in-kernel: gmem [k][n] fp32 -> smem [n][k] bf16 hi/lo
    for (int i = tid; i < NW * (K / 2); i += 256) {
        int n  = i >> 6;              // / (K/2)
        int k2 = i & 63;
        float v0 = W1g[(2 * k2)     * F_HID + n];
        float v1 = W1g[(2 * k2 + 1) * F_HID + n];
        __nv_bfloat16 h0 = __float2bfloat16(v0), h1 = __float2bfloat16(v1);
        uint32_t wh = packbf(h0, h1);
        uint32_t wl = packbf(__float2bfloat16(v0 - __bfloat162float(h0)),
                             __float2bfloat16(v1 - __bfloat162float(h1)));
        *(uint32_t*)(sm + OFF_WH + (n * SW + 2 * k2) * 2) = wh;
        *(uint32_t*)(sm + OFF_WL + (n * SW + 2 * k2) * 2) = wl;
    }

    float acc[4][NF][4];
#pragma unroll
    for (int mf = 0; mf < 4; mf++)
#pragma unroll
        for (int nf = 0; nf < NF; nf++)
#pragma unroll
            for (int j = 0; j < 4; j++) acc[mf][nf][j] = 0.f;

    const int arow  = tid >> 1;
    const int ahalf = tid & 1;
    const int grow  = rowBase + arow;
    const bool aok  = grow < N_NODES;

    for (int kc = 0; kc < K; kc += KC) {
        {
            const float4* src = (const float4*)&A[(size_t)(aok ? grow : 0) * K + kc + ahalf * 16];
#pragma unroll
            for (int i = 0; i < 4; i++) {
                float4 v = aok ? src[i] : make_float4(0.f, 0.f, 0.f, 0.f);
                __nv_bfloat16 hx = __float2bfloat16(v.x), hy = __float2bfloat16(v.y);
                __nv_bfloat16 hz = __float2bfloat16(v.z), hw = __float2bfloat16(v.w);
                uint32_t h0 = packbf(hx, hy), h1 = packbf(hz, hw);
                uint32_t l0 = packbf(__float2bfloat16(v.x - __bfloat162float(hx)),
                                     __float2bfloat16(v.y - __bfloat162float(hy)));
                uint32_t l1 = packbf(__float2bfloat16(v.z - __bfloat162float(hz)),
                                     __float2bfloat16(v.w - __bfloat162float(hw)));
                int col = ahalf * 16 + i * 4;
                *(uint32_t*)(sm + OFF_AH + (arow * SA + col) * 2)     = h0;
                *(uint32_t*)(sm + OFF_AH + (arow * SA + col + 2) * 2) = h1;
                *(uint32_t*)(sm + OFF_AL + (arow * SA + col) * 2)     = l0;
                *(uint32_t*)(sm + OFF_AL + (arow * SA + col + 2) * 2) = l1;
            }
        }
        __syncthreads();

#pragma unroll
        for (int ks = 0; ks < KC / 16; ks++) {
            const int k0 = ks * 16;
            uint32_t bh[NF][2], bl[NF][2];
#pragma unroll
            for (int nf = 0; nf < NF; nf++) {
                int n0 = nw * WN + nf * 8 + (lane >> 2);
                int bc = kc + k0 + (lane & 3) * 2;
                bh[nf][0] = *(const uint32_t*)(sm + OFF_WH + (n0 * SW + bc) * 2);
                bh[nf][1] = *(const uint32_t*)(sm + OFF_WH + (n0 * SW + bc + 8) * 2);
                bl[nf][0] = *(const uint32_t*)(sm + OFF_WL + (n0 * SW + bc) * 2);
                bl[nf][1] = *(const uint32_t*)(sm + OFF_WL + (n0 * SW + bc + 8) * 2);
            }
#pragma unroll
            for (int mf = 0; mf < 4; mf++) {
                int r0 = mw * 64 + mf * 16 + (lane >> 2);
                int ac = k0 + (lane & 3) * 2;
                uint32_t ah[4], al[4];
                ah[0] = *(const uint32_t*)(sm + OFF_AH + ((r0)     * SA + ac) * 2);
                ah[1] = *(const uint32_t*)(sm + OFF_AH + ((r0 + 8) * SA + ac) * 2);
                ah[2] = *(const uint32_t*)(sm + OFF_AH + ((r0)     * SA + ac + 8) * 2);
                ah[3] = *(const uint32_t*)(sm + OFF_AH + ((r0 + 8) * SA + ac + 8) * 2);
                al[0] = *(const uint32_t*)(sm + OFF_AL + ((r0)     * SA + ac) * 2);
                al[1] = *(const uint32_t*)(sm + OFF_AL + ((r0 + 8) * SA + ac) * 2);
                al[2] = *(const uint32_t*)(sm + OFF_AL + ((r0)     * SA + ac + 8) * 2);
                al[3] = *(const uint32_t*)(sm + OFF_AL + ((r0 + 8) * SA + ac + 8) * 2);
#pragma unroll
                for (int nf = 0; nf < NF; nf++) {
                    mma_bf16(acc[mf][nf], ah, bh[nf]);
                    mma_bf16(acc[mf][nf], ah, bl[nf]);
                    mma_bf16(acc[mf][nf], al, bh[nf]);
                }
            }
        }
        __syncthreads();
    }

    // epilogue: *dinv[row], convert fp16, store
#pragma unroll
    for (int mf = 0; mf < 4; mf++) {
        int r0 = rowBase + mw * 64 + mf * 16 + (lane >> 2);
        int r1 = r0 + 8;
        float dv0 = (r0 < N_NODES) ? g_dinv[r0] : 0.f;
        float dv1 = (r1 < N_NODES) ? g_dinv[r1] : 0.f;
#pragma unroll
        for (int nf = 0; nf < NF; nf++) {
            int col = nw * WN + nf * 8 + (lane & 3) * 2;
            if (r0 < N_NODES)
                *(__half2*)&g_hs1h[(size_t)r0 * NW + col] =
                    __floats2half2_rn(acc[mf][nf][0] * dv0, acc[mf][nf][1] * dv0);
            if (r1 < N_NODES)
                *(__half2*)&g_hs1h[(size_t)r1 * NW + col] =
                    __floats2half2_rn(acc[mf][nf][2] * dv1, acc[mf][nf][3] * dv1);
        }
    }
}

static constexpr int SMEM_G1 = 2 * (128 * 40 * 2) + 2 * (F_HID * 136 * 2);   // 90112

struct HxAttr {
    HxAttr() {
        cudaFuncSetAttribute(k_mma1_fill, cudaFuncAttributeMaxDynamicSharedMemorySize, SMEM_G1);
    }
};
static HxAttr g_attr;

// ================= aggregation layer 1 (UNCHANGED from R14 for clean profile) ==========
__global__ void k_agg1(const float* __restrict__ b1) {
    int w    = (blockIdx.x * blockDim.x + threadIdx.x) >> 5;
    int lane = threadIdx.x & 31;
    if (w >= N_NODES) return;
    const uint2* hs = (const uint2*)g_hs1h;      // 32 x 8B per row
    float4 acc;
    {
        uint2 u = hs[(size_t)w * 32 + lane];     // self-loop
        float2 f0 = __half22float2(*(__half2*)&u.x);
        float2 f1 = __half22float2(*(__half2*)&u.y);
        acc.x = f0.x; acc.y = f0.y; acc.z = f1.x; acc.w = f1.y;
    }
    int e  = g_off[w];
    int e1 = g_off[w + 1];
    for (; e + 7 < e1; e += 8) {
        int s[8];
#pragma unroll
        for (int q = 0; q < 8; q++) s[q] = g_srcs[e + q];
        uint2 u[8];
#pragma unroll
        for (int q = 0; q < 8; q++) u[q] = hs[(size_t)s[q] * 32 + lane];
#pragma unroll
        for (int q = 0; q < 8; q++) {
            float2 f0 = __half22float2(*(__half2*)&u[q].x);
            float2 f1 = __half22float2(*(__half2*)&u[q].y);
            acc.x += f0.x; acc.y += f0.y; acc.z += f1.x; acc.w += f1.y;
        }
    }
    for (; e < e1; e++) {
        uint2 u = hs[(size_t)g_srcs[e] * 32 + lane];
        float2 f0 = __half22float2(*(__half2*)&u.x);
        float2 f1 = __half22float2(*(__half2*)&u.y);
        acc.x += f0.x; acc.y += f0.y; acc.z += f1.x; acc.w += f1.y;
    }
    float dv = g_dinv[w];
    float4 bb = ((const float4*)b1)[lane];
    float4 o;
    o.x = fmaxf(fmaf(acc.x, dv, bb.x), 0.f);
    o.y = fmaxf(fmaf(acc.y, dv, bb.y), 0.f);
    o.z = fmaxf(fmaf(acc.z, dv, bb.z), 0.f);
    o.w = fmaxf(fmaf(acc.w, dv, bb.w), 0.f);
    ((float4*)g_agg1)[(size_t)w * 32 + lane] = o;
}

// ================= layer-2 GEMM: scalar FFMA2, fp16 output =================
__global__ void k_gemm2(const float* __restrict__ B) {
    constexpr int BM = 128, BN = 64, BK = 16, TM = 8, TN = 4;
    constexpr int TX  = BN / TN;      // 16
    constexpr int TY  = BM / TM;      // 16
    constexpr int NT  = TX * TY;      // 256
    constexpr int TN2 = TN / 2;
    const float* A = g_agg1;
    const int K = F_HID, Nc = F_OUT;
    __shared__ float As[BK][BM + 4];
    __shared__ __align__(16) float Bs[BK][BN];

    const int tid = threadIdx.x;
    const int tx  = tid % TX;
    const int ty  = tid / TX;
    const int rowBase = blockIdx.x * BM;

    u64 acc2[TM][TN2];
#pragma unroll
    for (int i = 0; i < TM; i++)
#pragma unroll
        for (int j = 0; j < TN2; j++) acc2[i][j] = 0ull;

    for (int kb = 0; kb < K; kb += BK) {
#pragma unroll
        for (int i = tid; i < BM * BK / 4; i += NT) {
            int r  = i / (BK / 4);
            int kq = (i % (BK / 4)) * 4;
            int gr = rowBase + r;
            float4 v = make_float4(0.f, 0.f, 0.f, 0.f);
            if (gr < N_NODES) v = *(const float4*)&A[gr * K + kb + kq];
            As[kq + 0][r] = v.x; As[kq + 1][r] = v.y;
            As[kq + 2][r] = v.z; As[kq + 3][r] = v.w;
        }
#pragma unroll
        for (int i = tid; i < BK * BN / 4; i += NT) {
            int k = (i * 4) / BN;
            int c = (i * 4) % BN;
            *(float4*)&Bs[k][c] = *(const float4*)&B[(kb + k) * Nc + c];
        }
        __syncthreads();
#pragma unroll
        for (int k = 0; k < BK; k++) {
            float a[TM];
#pragma unroll
            for (int i = 0; i < TM; i += 4) *(float4*)&a[i] = *(const float4*)&As[k][ty * TM + i];
            u64 aa[TM];
#pragma unroll
            for (int i = 0; i < TM; i++) aa[i] = pack2(a[i], a[i]);
            u64 bb[TN2];
#pragma unroll
            for (int j = 0; j < TN2; j++) bb[j] = *(const u64*)&Bs[k][tx * TN + 2 * j];
#pragma unroll
            for (int i = 0; i < TM; i++)
#pragma unroll
                for (int j = 0; j < TN2; j++) fma2(acc2[i][j], aa[i], bb[j]);
        }
        __syncthreads();
    }
#pragma unroll
    for (int i = 0; i < TM; i++) {
        int gr = rowBase + ty * TM + i;
        if (gr < N_NODES) {
            float dv = g_dinv[gr];
            float4 v;
            unpack2(acc2[i][0], v.x, v.y);
            unpack2(acc2[i][1], v.z, v.w);
            __half2 p0 = __floats2half2_rn(v.x * dv, v.y * dv);
            __half2 p1 = __floats2half2_rn(v.z * dv, v.w * dv);
            uint2 st;
            st.x = *(uint32_t*)&p0;
            st.y = *(uint32_t*)&p1;
            *(uint2*)&g_hs2h[(size_t)gr * Nc + tx * TN] = st;   // 8B aligned
        }
    }
}

// ================= aggregation layer 2: fp16 table (128B/row = 1 line) =================
__global__ void k_agg2(const float* __restrict__ b2, float* __restrict__ out) {
    int w    = (blockIdx.x * blockDim.x + threadIdx.x) >> 5;
    int lane = threadIdx.x & 31;
    if (w >= N_NODES) return;
    const uint32_t* hs = (const uint32_t*)g_hs2h;   // 32 x 4B per row
    float2 acc;
    {
        uint32_t u = hs[(size_t)w * 32 + lane];
        acc = __half22float2(*(__half2*)&u);
    }
    int e  = g_off[w];
    int e1 = g_off[w + 1];
    for (; e + 7 < e1; e += 8) {
        int s[8];
#pragma unroll
        for (int q = 0; q < 8; q++) s[q] = g_srcs[e + q];
        uint32_t u[8];
#pragma unroll
        for (int q = 0; q < 8; q++) u[q] = hs[(size_t)s[q] * 32 + lane];
#pragma unroll
        for (int q = 0; q < 8; q++) {
            float2 f = __half22float2(*(__half2*)&u[q]);
            acc.x += f.x; acc.y += f.y;
        }
    }
    for (; e < e1; e++) {
        uint32_t u = hs[(size_t)g_srcs[e] * 32 + lane];
        float2 f = __half22float2(*(__half2*)&u);
        acc.x += f.x; acc.y += f.y;
    }
    float dv = g_dinv[w];
    float2 bb = ((const float2*)b2)[lane];
    float2 o;
    o.x = fmaf(acc.x, dv, bb.x);
    o.y = fmaf(acc.y, dv, bb.y);
    ((float2*)out)[(size_t)w * 32 + lane] = o;
}

// ================= launcher: 6 kernels, k_agg1 at submission index 3 =================
extern "C" void kernel_launch(void* const* d_in, const int* in_sizes, int n_in,
                              void* d_out, int out_size) {
    const float* x  = (const float*)d_in[0];
    const int*   ei = (const int*)d_in[1];
    const float* W1 = (const float*)d_in[2];
    const float* b1 = (const float*)d_in[3];
    const float* W2 = (const float*)d_in[4];
    const float* b2 = (const float*)d_in[5];
    float* out = (float*)d_out;

    k_hist      <<<NB_E4, 256>>>(ei);                    // 0
    k_scan_all  <<<1, 1024>>>();                         // 1
    k_mma1_fill <<<NB_E4, 256, SMEM_G1>>>(x, ei, W1);    // 2  (fill + GEMM1 fused)
    k_agg1      <<<(N_NODES + 7) / 8, 256>>>(b1);        // 3  <- ncu capture slot
    k_gemm2     <<<NB_G, 256>>>(W2);                     // 4
    k_agg2      <<<(N_NODES + 7) / 8, 256>>>(b2, out);   // 5
}

// round 16
// speedup vs baseline: 1.9601x; 1.9601x over previous
#include <cuda_runtime.h>
#include <cuda_bf16.h>
#include <cuda_fp16.h>
#include <cstdint>

#define N_NODES 100000
#define N_EDGES 1600000
#define F_IN    128
#define F_HID   128
#define F_OUT   64

#define NB_G  ((N_NODES + 127) / 128)          // 782
#define NB_E4 ((N_EDGES / 4 + 255) / 256)      // 1563
#define NB_N  ((N_NODES + 255) / 256)          // 391

typedef unsigned long long u64;

// ---------------- packed f32x2 helpers ----------------
__device__ __forceinline__ u64 pack2(float lo, float hi) {
    u64 r; asm("mov.b64 %0, {%1, %2};" : "=l"(r) : "f"(lo), "f"(hi)); return r;
}
__device__ __forceinline__ void fma2(u64& d, u64 a, u64 b) {
    asm("fma.rn.f32x2 %0, %1, %2, %3;" : "=l"(d) : "l"(a), "l"(b), "l"(d));
}
__device__ __forceinline__ void unpack2(u64 v, float& lo, float& hi) {
    asm("mov.b64 {%0, %1}, %2;" : "=f"(lo), "=f"(hi) : "l"(v));
}
__device__ __forceinline__ uint32_t packbf(__nv_bfloat16 a, __nv_bfloat16 b) {
    return ((uint32_t)__bfloat16_as_ushort(b) << 16) | __bfloat16_as_ushort(a);
}
__device__ __forceinline__ void mma_bf16(float* d, const uint32_t* a, const uint32_t* b) {
    asm volatile(
        "mma.sync.aligned.m16n8k16.row.col.f32.bf16.bf16.f32 "
        "{%0,%1,%2,%3}, {%4,%5,%6,%7}, {%8,%9}, {%0,%1,%2,%3};"
        : "+f"(d[0]), "+f"(d[1]), "+f"(d[2]), "+f"(d[3])
        : "r"(a[0]), "r"(a[1]), "r"(a[2]), "r"(a[3]), "r"(b[0]), "r"(b[1]));
}

// ---------------- static device scratch ----------------
// g_cnt zero-initialized at module load; k_offsets re-zeroes after consuming.
__device__ int   g_cnt[N_NODES];
__device__ int   g_off[N_NODES];     // start of each node's edge range (NOT monotone)
__device__ int   g_cur[N_NODES];     // fill cursor; after k_fill == end of range
__device__ int   g_total;            // global range allocator (reset in k_hist)
__device__ int   g_srcs[N_EDGES];
__device__ float g_dinv[N_NODES];
__device__ __align__(16) __half g_hs1h[N_NODES * F_HID];   // fp16 dinv-scaled x@W1
__device__ __align__(16) float  g_agg1[N_NODES * F_HID];   // relu(layer1 out), fp32
__device__ __align__(16) __half g_hs2h[N_NODES * F_OUT];   // fp16 dinv-scaled agg1@W2

// ---------------- CSR: histogram (+ reset allocator) ----------------
__global__ void k_hist(const int* __restrict__ ei) {
    if (blockIdx.x == 0 && threadIdx.x == 0) g_total = 0;   // consumed later by k_offsets
    int e4 = blockIdx.x * blockDim.x + threadIdx.x;
    if (e4 * 4 < N_EDGES) {
        int4 d = *(const int4*)&ei[N_EDGES + e4 * 4];
        if ((unsigned)d.x < N_NODES) atomicAdd(&g_cnt[d.x], 1);
        if ((unsigned)d.y < N_NODES) atomicAdd(&g_cnt[d.y], 1);
        if ((unsigned)d.z < N_NODES) atomicAdd(&g_cnt[d.z], 1);
        if ((unsigned)d.w < N_NODES) atomicAdd(&g_cnt[d.w], 1);
    }
}

// ---------------- CSR: parallel range allocation (replaces serial scan) ----------------
// Ranges need NOT be monotone across nodes — only contiguous per node.
// Block-aggregated: warp shuffle-scan + cross-warp smem scan + ONE atomicAdd per block.
__global__ void k_offsets() {
    const int i    = blockIdx.x * 256 + threadIdx.x;
    const int lane = threadIdx.x & 31;
    const int wid  = threadIdx.x >> 5;
    int c = (i < N_NODES) ? g_cnt[i] : 0;

    // warp-inclusive scan of c
    int pre = c;
#pragma unroll
    for (int d = 1; d < 32; d <<= 1) {
        int v = __shfl_up_sync(0xFFFFFFFFu, pre, d);
        if (lane >= d) pre += v;
    }
    __shared__ int wsum[8], woff[8], base;
    if (lane == 31) wsum[wid] = pre;
    __syncthreads();
    if (threadIdx.x == 0) {
        int r = 0;
#pragma unroll
        for (int q = 0; q < 8; q++) { woff[q] = r; r += wsum[q]; }
        base = atomicAdd(&g_total, r);
    }
    __syncthreads();
    if (i < N_NODES) {
        int ofs = base + woff[wid] + pre - c;   // exclusive prefix within block + base
        g_off[i]  = ofs;
        g_cur[i]  = ofs;
        g_dinv[i] = rsqrtf((float)(c + 1));
        g_cnt[i]  = 0;                          // ready for next graph replay
    }
}

// ---------------- CSR: fill ----------------
__global__ void k_fill(const int* __restrict__ ei) {
    int e4 = blockIdx.x * blockDim.x + threadIdx.x;
    if (e4 * 4 < N_EDGES) {
        int4 s = *(const int4*)&ei[e4 * 4];
        int4 d = *(const int4*)&ei[N_EDGES + e4 * 4];
        if ((unsigned)d.x < N_NODES && (unsigned)s.x < N_NODES)
            g_srcs[atomicAdd(&g_cur[d.x], 1)] = s.x;
        if ((unsigned)d.y < N_NODES && (unsigned)s.y < N_NODES)
            g_srcs[atomicAdd(&g_cur[d.y], 1)] = s.y;
        if ((unsigned)d.z < N_NODES && (unsigned)s.z < N_NODES)
            g_srcs[atomicAdd(&g_cur[d.z], 1)] = s.z;
        if ((unsigned)d.w < N_NODES && (unsigned)s.w < N_NODES)
            g_srcs[atomicAdd(&g_cur[d.w], 1)] = s.w;
    }
}

// ================= layer-1 GEMM: split-bf16 mma.sync, fp16 output =================
// hs1h[m,n] = fp16(dinv[m] * (x[m,:]@W1[:,n])); W1 split/transposed in-kernel.
__global__ __launch_bounds__(256) void k_mma1(
    const float* __restrict__ A, const float* __restrict__ W1g)
{
    constexpr int NW = F_HID;
    constexpr int K  = 128;
    constexpr int KC = 32;
    constexpr int SA = KC + 8;
    constexpr int SW = K + 8;
    constexpr int WN = NW / 4;        // 32
    constexpr int NF = WN / 8;        // 4
    constexpr int OFF_AH = 0;
    constexpr int OFF_AL = 128 * SA * 2;
    constexpr int OFF_WH = 2 * 128 * SA * 2;
    constexpr int OFF_WL = OFF_WH + NW * SW * 2;

    extern __shared__ __align__(16) char sm[];
    const int tid  = threadIdx.x;
    const int wid  = tid >> 5;
    const int lane = tid & 31;
    const int mw   = wid >> 2;
    const int nw   = wid & 3;
    const int rowBase = blockIdx.x * 128;

    // W1 split/transpose: gmem [k][n] fp32 -> smem [n][k] bf16 hi/lo
    for (int i = tid; i < NW * (K / 2); i += 256) {
        int n  = i >> 6;
        int k2 = i & 63;
        float v0 = W1g[(2 * k2)     * F_HID + n];
        float v1 = W1g[(2 * k2 + 1) * F_HID + n];
        __nv_bfloat16 h0 = __float2bfloat16(v0), h1 = __float2bfloat16(v1);
        uint32_t wh = packbf(h0, h1);
        uint32_t wl = packbf(__float2bfloat16(v0 - __bfloat162float(h0)),
                             __float2bfloat16(v1 - __bfloat162float(h1)));
        *(uint32_t*)(sm + OFF_WH + (n * SW + 2 * k2) * 2) = wh;
        *(uint32_t*)(sm + OFF_WL + (n * SW + 2 * k2) * 2) = wl;
    }

    float acc[4][NF][4];
#pragma unroll
    for (int mf = 0; mf < 4; mf++)
#pragma unroll
        for (int nf = 0; nf < NF; nf++)
#pragma unroll
            for (int j = 0; j < 4; j++) acc[mf][nf][j] = 0.f;

    const int arow  = tid >> 1;
    const int ahalf = tid & 1;
    const int grow  = rowBase + arow;
    const bool aok  = grow < N_NODES;

    for (int kc = 0; kc < K; kc += KC) {
        {
            const float4* src = (const float4*)&A[(size_t)(aok ? grow : 0) * K + kc + ahalf * 16];
#pragma unroll
            for (int i = 0; i < 4; i++) {
                float4 v = aok ? src[i] : make_float4(0.f, 0.f, 0.f, 0.f);
                __nv_bfloat16 hx = __float2bfloat16(v.x), hy = __float2bfloat16(v.y);
                __nv_bfloat16 hz = __float2bfloat16(v.z), hw = __float2bfloat16(v.w);
                uint32_t h0 = packbf(hx, hy), h1 = packbf(hz, hw);
                uint32_t l0 = packbf(__float2bfloat16(v.x - __bfloat162float(hx)),
                                     __float2bfloat16(v.y - __bfloat162float(hy)));
                uint32_t l1 = packbf(__float2bfloat16(v.z - __bfloat162float(hz)),
                                     __float2bfloat16(v.w - __bfloat162float(hw)));
                int col = ahalf * 16 + i * 4;
                *(uint32_t*)(sm + OFF_AH + (arow * SA + col) * 2)     = h0;
                *(uint32_t*)(sm + OFF_AH + (arow * SA + col + 2) * 2) = h1;
                *(uint32_t*)(sm + OFF_AL + (arow * SA + col) * 2)     = l0;
                *(uint32_t*)(sm + OFF_AL + (arow * SA + col + 2) * 2) = l1;
            }
        }
        __syncthreads();

#pragma unroll
        for (int ks = 0; ks < KC / 16; ks++) {
            const int k0 = ks * 16;
            uint32_t bh[NF][2], bl[NF][2];
#pragma unroll
            for (int nf = 0; nf < NF; nf++) {
                int n0 = nw * WN + nf * 8 + (lane >> 2);
                int bc = kc + k0 + (lane & 3) * 2;
                bh[nf][0] = *(const uint32_t*)(sm + OFF_WH + (n0 * SW + bc) * 2);
                bh[nf][1] = *(const uint32_t*)(sm + OFF_WH + (n0 * SW + bc + 8) * 2);
                bl[nf][0] = *(const uint32_t*)(sm + OFF_WL + (n0 * SW + bc) * 2);
                bl[nf][1] = *(const uint32_t*)(sm + OFF_WL + (n0 * SW + bc + 8) * 2);
            }
#pragma unroll
            for (int mf = 0; mf < 4; mf++) {
                int r0 = mw * 64 + mf * 16 + (lane >> 2);
                int ac = k0 + (lane & 3) * 2;
                uint32_t ah[4], al[4];
                ah[0] = *(const uint32_t*)(sm + OFF_AH + ((r0)     * SA + ac) * 2);
                ah[1] = *(const uint32_t*)(sm + OFF_AH + ((r0 + 8) * SA + ac) * 2);
                ah[2] = *(const uint32_t*)(sm + OFF_AH + ((r0)     * SA + ac + 8) * 2);
                ah[3] = *(const uint32_t*)(sm + OFF_AH + ((r0 + 8) * SA + ac + 8) * 2);
                al[0] = *(const uint32_t*)(sm + OFF_AL + ((r0)     * SA + ac) * 2);
                al[1] = *(const uint32_t*)(sm + OFF_AL + ((r0 + 8) * SA + ac) * 2);
                al[2] = *(const uint32_t*)(sm + OFF_AL + ((r0)     * SA + ac + 8) * 2);
                al[3] = *(const uint32_t*)(sm + OFF_AL + ((r0 + 8) * SA + ac + 8) * 2);
#pragma unroll
                for (int nf = 0; nf < NF; nf++) {
                    mma_bf16(acc[mf][nf], ah, bh[nf]);
                    mma_bf16(acc[mf][nf], ah, bl[nf]);
                    mma_bf16(acc[mf][nf], al, bh[nf]);
                }
            }
        }
        __syncthreads();
    }

#pragma unroll
    for (int mf = 0; mf < 4; mf++) {
        int r0 = rowBase + mw * 64 + mf * 16 + (lane >> 2);
        int r1 = r0 + 8;
        float dv0 = (r0 < N_NODES) ? g_dinv[r0] : 0.f;
        float dv1 = (r1 < N_NODES) ? g_dinv[r1] : 0.f;
#pragma unroll
        for (int nf = 0; nf < NF; nf++) {
            int col = nw * WN + nf * 8 + (lane & 3) * 2;
            if (r0 < N_NODES)
                *(__half2*)&g_hs1h[(size_t)r0 * NW + col] =
                    __floats2half2_rn(acc[mf][nf][0] * dv0, acc[mf][nf][1] * dv0);
            if (r1 < N_NODES)
                *(__half2*)&g_hs1h[(size_t)r1 * NW + col] =
                    __floats2half2_rn(acc[mf][nf][2] * dv1, acc[mf][nf][3] * dv1);
        }
    }
}

static constexpr int SMEM_G1 = 2 * (128 * 40 * 2) + 2 * (F_HID * 136 * 2);   // 90112

struct HxAttr {
    HxAttr() {
        cudaFuncSetAttribute(k_mma1, cudaFuncAttributeMaxDynamicSharedMemorySize, SMEM_G1);
    }
};
static HxAttr g_attr;

// ================= aggregation layer 1: fp16 table, range [g_off, g_cur) =================
__global__ void k_agg1(const float* __restrict__ b1) {
    int w    = (blockIdx.x * blockDim.x + threadIdx.x) >> 5;
    int lane = threadIdx.x & 31;
    if (w >= N_NODES) return;
    const uint2* hs = (const uint2*)g_hs1h;      // 32 x 8B per row
    float4 acc;
    {
        uint2 u = hs[(size_t)w * 32 + lane];     // self-loop
        float2 f0 = __half22float2(*(__half2*)&u.x);
        float2 f1 = __half22float2(*(__half2*)&u.y);
        acc.x = f0.x; acc.y = f0.y; acc.z = f1.x; acc.w = f1.y;
    }
    int e  = g_off[w];
    int e1 = g_cur[w];                            // end of range after fill
    for (; e + 7 < e1; e += 8) {
        int s[8];
#pragma unroll
        for (int q = 0; q < 8; q++) s[q] = g_srcs[e + q];
        uint2 u[8];
#pragma unroll
        for (int q = 0; q < 8; q++) u[q] = hs[(size_t)s[q] * 32 + lane];
#pragma unroll
        for (int q = 0; q < 8; q++) {
            float2 f0 = __half22float2(*(__half2*)&u[q].x);
            float2 f1 = __half22float2(*(__half2*)&u[q].y);
            acc.x += f0.x; acc.y += f0.y; acc.z += f1.x; acc.w += f1.y;
        }
    }
    for (; e < e1; e++) {
        uint2 u = hs[(size_t)g_srcs[e] * 32 + lane];
        float2 f0 = __half22float2(*(__half2*)&u.x);
        float2 f1 = __half22float2(*(__half2*)&u.y);
        acc.x += f0.x; acc.y += f0.y; acc.z += f1.x; acc.w += f1.y;
    }
    float dv = g_dinv[w];
    float4 bb = ((const float4*)b1)[lane];
    float4 o;
    o.x = fmaxf(fmaf(acc.x, dv, bb.x), 0.f);
    o.y = fmaxf(fmaf(acc.y, dv, bb.y), 0.f);
    o.z = fmaxf(fmaf(acc.z, dv, bb.z), 0.f);
    o.w = fmaxf(fmaf(acc.w, dv, bb.w), 0.f);
    ((float4*)g_agg1)[(size_t)w * 32 + lane] = o;
}

// ================= layer-2 GEMM: scalar FFMA2, fp16 output =================
__global__ void k_gemm2(const float* __restrict__ B) {
    constexpr int BM = 128, BN = 64, BK = 16, TM = 8, TN = 4;
    constexpr int TX  = BN / TN;
    constexpr int TY  = BM / TM;
    constexpr int NT  = TX * TY;
    constexpr int TN2 = TN / 2;
    const float* A = g_agg1;
    const int K = F_HID, Nc = F_OUT;
    __shared__ float As[BK][BM + 4];
    __shared__ __align__(16) float Bs[BK][BN];

    const int tid = threadIdx.x;
    const int tx  = tid % TX;
    const int ty  = tid / TX;
    const int rowBase = blockIdx.x * BM;

    u64 acc2[TM][TN2];
#pragma unroll
    for (int i = 0; i < TM; i++)
#pragma unroll
        for (int j = 0; j < TN2; j++) acc2[i][j] = 0ull;

    for (int kb = 0; kb < K; kb += BK) {
#pragma unroll
        for (int i = tid; i < BM * BK / 4; i += NT) {
            int r  = i / (BK / 4);
            int kq = (i % (BK / 4)) * 4;
            int gr = rowBase + r;
            float4 v = make_float4(0.f, 0.f, 0.f, 0.f);
            if (gr < N_NODES) v = *(const float4*)&A[gr * K + kb + kq];
            As[kq + 0][r] = v.x; As[kq + 1][r] = v.y;
            As[kq + 2][r] = v.z; As[kq + 3][r] = v.w;
        }
#pragma unroll
        for (int i = tid; i < BK * BN / 4; i += NT) {
            int k = (i * 4) / BN;
            int c = (i * 4) % BN;
            *(float4*)&Bs[k][c] = *(const float4*)&B[(kb + k) * Nc + c];
        }
        __syncthreads();
#pragma unroll
        for (int k = 0; k < BK; k++) {
            float a[TM];
#pragma unroll
            for (int i = 0; i < TM; i += 4) *(float4*)&a[i] = *(const float4*)&As[k][ty * TM + i];
            u64 aa[TM];
#pragma unroll
            for (int i = 0; i < TM; i++) aa[i] = pack2(a[i], a[i]);
            u64 bb[TN2];
#pragma unroll
            for (int j = 0; j < TN2; j++) bb[j] = *(const u64*)&Bs[k][tx * TN + 2 * j];
#pragma unroll
            for (int i = 0; i < TM; i++)
#pragma unroll
                for (int j = 0; j < TN2; j++) fma2(acc2[i][j], aa[i], bb[j]);
        }
        __syncthreads();
    }
#pragma unroll
    for (int i = 0; i < TM; i++) {
        int gr = rowBase + ty * TM + i;
        if (gr < N_NODES) {
            float dv = g_dinv[gr];
            float4 v;
            unpack2(acc2[i][0], v.x, v.y);
            unpack2(acc2[i][1], v.z, v.w);
            __half2 p0 = __floats2half2_rn(v.x * dv, v.y * dv);
            __half2 p1 = __floats2half2_rn(v.z * dv, v.w * dv);
            uint2 st;
            st.x = *(uint32_t*)&p0;
            st.y = *(uint32_t*)&p1;
            *(uint2*)&g_hs2h[(size_t)gr * Nc + tx * TN] = st;
        }
    }
}

// ================= aggregation layer 2: fp16 table, range [g_off, g_cur) =================
__global__ void k_agg2(const float* __restrict__ b2, float* __restrict__ out) {
    int w    = (blockIdx.x * blockDim.x + threadIdx.x) >> 5;
    int lane = threadIdx.x & 31;
    if (w >= N_NODES) return;
    const uint32_t* hs = (const uint32_t*)g_hs2h;   // 32 x 4B per row
    float2 acc;
    {
        uint32_t u = hs[(size_t)w * 32 + lane];
        acc = __half22float2(*(__half2*)&u);
    }
    int e  = g_off[w];
    int e1 = g_cur[w];
    for (; e + 7 < e1; e += 8) {
        int s[8];
#pragma unroll
        for (int q = 0; q < 8; q++) s[q] = g_srcs[e + q];
        uint32_t u[8];
#pragma unroll
        for (int q = 0; q < 8; q++) u[q] = hs[(size_t)s[q] * 32 + lane];
#pragma unroll
        for (int q = 0; q < 8; q++) {
            float2 f = __half22float2(*(__half2*)&u[q]);
            acc.x += f.x; acc.y += f.y;
        }
    }
    for (; e < e1; e++) {
        uint32_t u = hs[(size_t)g_srcs[e] * 32 + lane];
        float2 f = __half22float2(*(__half2*)&u);
        acc.x += f.x; acc.y += f.y;
    }
    float dv = g_dinv[w];
    float2 bb = ((const float2*)b2)[lane];
    float2 o;
    o.x = fmaf(acc.x, dv, bb.x);
    o.y = fmaf(acc.y, dv, bb.y);
    ((float2*)out)[(size_t)w * 32 + lane] = o;
}

// ================= launcher: k_fill at submission index 3 for ncu =================
extern "C" void kernel_launch(void* const* d_in, const int* in_sizes, int n_in,
                              void* d_out, int out_size) {
    const float* x  = (const float*)d_in[0];
    const int*   ei = (const int*)d_in[1];
    const float* W1 = (const float*)d_in[2];
    const float* b1 = (const float*)d_in[3];
    const float* W2 = (const float*)d_in[4];
    const float* b2 = (const float*)d_in[5];
    float* out = (float*)d_out;

    k_hist    <<<NB_E4, 256>>>(ei);                    // 0
    k_offsets <<<NB_N, 256>>>();                       // 1  (parallel scan replacement)
    k_mma1    <<<NB_G, 256, SMEM_G1>>>(x, W1);         // 2
    k_fill    <<<NB_E4, 256>>>(ei);                    // 3  <- ncu capture slot
    k_agg1    <<<(N_NODES + 7) / 8, 256>>>(b1);        // 4
    k_gemm2   <<<NB_G, 256>>>(W2);                     // 5
    k_agg2    <<<(N_NODES + 7) / 8, 256>>>(b2, out);   // 6
}